// round 16
// baseline (speedup 1.0000x reference)
#include <cuda_runtime.h>
#include <cuda_bf16.h>
#include <cstdint>

// Problem constants
#define Bc  4
#define Sc  2048
#define Hc  768
#define NHc 12
#define DHc 64
#define Mc  (Bc * Sc)          // 8192
#define SCALE 0.125f
#define LOG2E 1.4426950408889634f

typedef __nv_bfloat16 bf16;

// =================== helpers ================================================
__device__ __forceinline__ uint32_t smem_u32(const void* p) {
    uint32_t a;
    asm("{ .reg .u64 t; cvta.to.shared.u64 t, %1; cvt.u32.u64 %0, t; }" : "=r"(a) : "l"(p));
    return a;
}
__device__ __forceinline__ uint32_t lds32(uint32_t addr) {
    uint32_t v; asm volatile("ld.shared.b32 %0, [%1];" : "=r"(v) : "r"(addr)); return v;
}
__device__ __forceinline__ void ldm4(uint32_t* r, uint32_t addr) {
    asm volatile("ldmatrix.sync.aligned.m8n8.x4.shared.b16 {%0,%1,%2,%3}, [%4];"
        : "=r"(r[0]), "=r"(r[1]), "=r"(r[2]), "=r"(r[3]) : "r"(addr));
}
__device__ __forceinline__ void ldm2(uint32_t* r, uint32_t addr) {
    asm volatile("ldmatrix.sync.aligned.m8n8.x2.shared.b16 {%0,%1}, [%2];"
        : "=r"(r[0]), "=r"(r[1]) : "r"(addr));
}
__device__ __forceinline__ void mma_bf16(float* d, const uint32_t* a, uint32_t b0, uint32_t b1) {
    asm volatile("mma.sync.aligned.m16n8k16.row.col.f32.bf16.bf16.f32 "
        "{%0,%1,%2,%3}, {%4,%5,%6,%7}, {%8,%9}, {%0,%1,%2,%3};"
        : "+f"(d[0]), "+f"(d[1]), "+f"(d[2]), "+f"(d[3])
        : "r"(a[0]), "r"(a[1]), "r"(a[2]), "r"(a[3]), "r"(b0), "r"(b1));
}
__device__ __forceinline__ void mma_tf32(float* d, const uint32_t* a, uint32_t b0, uint32_t b1) {
    asm volatile("mma.sync.aligned.m16n8k8.row.col.f32.tf32.tf32.f32 "
        "{%0,%1,%2,%3}, {%4,%5,%6,%7}, {%8,%9}, {%0,%1,%2,%3};"
        : "+f"(d[0]), "+f"(d[1]), "+f"(d[2]), "+f"(d[3])
        : "r"(a[0]), "r"(a[1]), "r"(a[2]), "r"(a[3]), "r"(b0), "r"(b1));
}
__device__ __forceinline__ uint32_t f2tf32(float v) {
    uint32_t u; asm("cvt.rna.tf32.f32 %0, %1;" : "=r"(u) : "f"(v)); return u;
}
__device__ __forceinline__ float ex2f(float x) {
    float y; asm("ex2.approx.f32 %0, %1;" : "=f"(y) : "f"(x)); return y;
}
// cp.async (sm_80 baseline -> valid on compute_103)
__device__ __forceinline__ void cp16(uint32_t dst, const void* src) {
    asm volatile("cp.async.cg.shared.global [%0], [%1], 16;" :: "r"(dst), "l"(src));
}
#define CP_COMMIT() asm volatile("cp.async.commit_group;" ::: "memory")
#define CP_WAIT(n)  asm volatile("cp.async.wait_group %0;" :: "n"(n) : "memory")

// =================== scratch (device globals) ================================
__device__ float g_Qf[(size_t)Bc * NHc * Sc * DHc];   // tf32-rounded, Q pre-scaled by SCALE*log2e
__device__ float g_Kf[(size_t)Bc * NHc * Sc * DHc];
__device__ float g_Vf[(size_t)Bc * NHc * Sc * DHc];
__device__ bf16 g_Ahi[(size_t)Mc * Hc], g_Alo[(size_t)Mc * Hc];          // attn out split
__device__ bf16 g_Xhi[(size_t)Mc * Hc], g_Xlo[(size_t)Mc * Hc];          // x split
__device__ bf16 g_WtHi[(size_t)4 * Hc * Hc], g_WtLo[(size_t)4 * Hc * Hc]; // W^T [z][n][k]

// =================== split kernels ==========================================
__device__ __forceinline__ void split1(float v, bf16& h, bf16& l) {
    h = __float2bfloat16(v);
    l = __float2bfloat16(v - __bfloat162float(h));
}

__global__ __launch_bounds__(256)
void split_x_kernel(const float* __restrict__ X) {
    const int idx = blockIdx.x * 256 + threadIdx.x;
    float4 v = ((const float4*)X)[idx];
    bf16 h0,h1,h2,h3,l0,l1,l2,l3;
    split1(v.x,h0,l0); split1(v.y,h1,l1); split1(v.z,h2,l2); split1(v.w,h3,l3);
    ((__nv_bfloat162*)g_Xhi)[2*idx]   = __halves2bfloat162(h0,h1);
    ((__nv_bfloat162*)g_Xhi)[2*idx+1] = __halves2bfloat162(h2,h3);
    ((__nv_bfloat162*)g_Xlo)[2*idx]   = __halves2bfloat162(l0,l1);
    ((__nv_bfloat162*)g_Xlo)[2*idx+1] = __halves2bfloat162(l2,l3);
}

// transpose + split: Wt[n][k] = W[k][n]
__global__ __launch_bounds__(256)
void split_w_kernel(const float* __restrict__ Wq, const float* __restrict__ Wk,
                    const float* __restrict__ Wv, const float* __restrict__ Wo) {
    __shared__ float t[32][33];
    const int z = blockIdx.z;
    const float* W = (z == 0) ? Wq : (z == 1) ? Wk : (z == 2) ? Wv : Wo;
    bf16* hi = g_WtHi + (size_t)z * Hc * Hc;
    bf16* lo = g_WtLo + (size_t)z * Hc * Hc;
    const int bx = blockIdx.x * 32;
    const int by = blockIdx.y * 32;
    const int tx = threadIdx.x & 31, ty = (threadIdx.x >> 5) * 4;
    #pragma unroll
    for (int j = 0; j < 4; j++)
        t[ty + j][tx] = W[(size_t)(by + ty + j) * Hc + bx + tx];
    __syncthreads();
    #pragma unroll
    for (int j = 0; j < 4; j++) {
        float v = t[tx][ty + j];
        bf16 h, l; split1(v, h, l);
        hi[(size_t)(bx + ty + j) * Hc + by + tx] = h;
        lo[(size_t)(bx + ty + j) * Hc + by + tx] = l;
    }
}

// =================== mma.sync bf16 GEMM (split fp32, static smem) ===========
// MODE 0: fp32 (+bias) row-major.  MODE 1: tf32-rounded fp32 (+bias,*scale)
// into head layout [b*NH+h][s][d].
#define PADK 40

template <int MODE>
__device__ __forceinline__ void mma_gemm_body(
    const bf16* __restrict__ Ahi, const bf16* __restrict__ Alo,
    const bf16* __restrict__ Bhi, const bf16* __restrict__ Blo,
    const float* __restrict__ bias, float scale,
    float* __restrict__ outF)
{
    __shared__ bf16 sAh[128][PADK], sAl[128][PADK];
    __shared__ bf16 sBh[128][PADK], sBl[128][PADK];

    const int tid = threadIdx.x, lane = tid & 31, wid = tid >> 5;
    const int warp_m = wid >> 1, warp_n = wid & 1;
    const int m0 = blockIdx.y * 128, n0 = blockIdx.x * 128;

    float d[2][8][4];
    #pragma unroll
    for (int mt = 0; mt < 2; mt++)
        #pragma unroll
        for (int nt = 0; nt < 8; nt++)
            #pragma unroll
            for (int i = 0; i < 4; i++) d[mt][nt][i] = 0.f;

    const int lr = lane & 15, chk = lane >> 4;
    const uint32_t baseAh = smem_u32(&sAh[0][0]);
    const uint32_t baseAl = smem_u32(&sAl[0][0]);
    const uint32_t baseBh = smem_u32(&sBh[0][0]);
    const uint32_t baseBl = smem_u32(&sBl[0][0]);

    #pragma unroll 1
    for (int c = 0; c < Hc / 32; c++) {
        const int k0 = c * 32;
        #pragma unroll
        for (int p = 0; p < 2; p++) {
            const int idx = tid + p * 256;
            const int r = idx >> 2, cc = idx & 3;
            const size_t goA = (size_t)(m0 + r) * Hc + k0 + cc * 8;
            const size_t goB = (size_t)(n0 + r) * Hc + k0 + cc * 8;
            *(uint4*)&sAh[r][cc * 8] = *(const uint4*)(Ahi + goA);
            *(uint4*)&sAl[r][cc * 8] = *(const uint4*)(Alo + goA);
            *(uint4*)&sBh[r][cc * 8] = *(const uint4*)(Bhi + goB);
            *(uint4*)&sBl[r][cc * 8] = *(const uint4*)(Blo + goB);
        }
        __syncthreads();

        #pragma unroll
        for (int s = 0; s < 2; s++) {
            const int kc = s * 16;
            uint32_t ah[2][4], al[2][4];
            #pragma unroll
            for (int mt = 0; mt < 2; mt++) {
                const uint32_t off =
                    (uint32_t)(((warp_m * 32 + mt * 16 + lr) * PADK + kc + chk * 8) * 2);
                ldm4(ah[mt], baseAh + off);
                ldm4(al[mt], baseAl + off);
            }
            #pragma unroll
            for (int nt2 = 0; nt2 < 4; nt2++) {
                const uint32_t off =
                    (uint32_t)(((warp_n * 64 + nt2 * 16 + lr) * PADK + kc + chk * 8) * 2);
                uint32_t tb[4];
                ldm4(tb, baseBh + off);
                #pragma unroll
                for (int mt = 0; mt < 2; mt++) {
                    mma_bf16(d[mt][nt2 * 2],     ah[mt], tb[0], tb[2]);
                    mma_bf16(d[mt][nt2 * 2 + 1], ah[mt], tb[1], tb[3]);
                    mma_bf16(d[mt][nt2 * 2],     al[mt], tb[0], tb[2]);
                    mma_bf16(d[mt][nt2 * 2 + 1], al[mt], tb[1], tb[3]);
                }
                ldm4(tb, baseBl + off);
                #pragma unroll
                for (int mt = 0; mt < 2; mt++) {
                    mma_bf16(d[mt][nt2 * 2],     ah[mt], tb[0], tb[2]);
                    mma_bf16(d[mt][nt2 * 2 + 1], ah[mt], tb[1], tb[3]);
                }
            }
        }
        __syncthreads();
    }

    const int g = lane >> 2, tg = lane & 3;
    #pragma unroll
    for (int mt = 0; mt < 2; mt++) {
        #pragma unroll
        for (int nt = 0; nt < 8; nt++) {
            const int n  = n0 + warp_n * 64 + nt * 8 + tg * 2;
            const float b0 = bias[n], b1 = bias[n + 1];
            #pragma unroll
            for (int half = 0; half < 2; half++) {
                const int m = m0 + warp_m * 32 + mt * 16 + g + half * 8;
                float v0 = d[mt][nt][half * 2 + 0] + b0;
                float v1 = d[mt][nt][half * 2 + 1] + b1;
                if (MODE == 0) {
                    float2 v; v.x = v0; v.y = v1;
                    *(float2*)(outF + (size_t)m * Hc + n) = v;
                } else {
                    v0 *= scale; v1 *= scale;
                    float2 v;
                    v.x = __uint_as_float(f2tf32(v0));
                    v.y = __uint_as_float(f2tf32(v1));
                    const int bb = m >> 11, sI = m & (Sc - 1);
                    const int h = n >> 6, dd = n & 63;
                    const size_t o = (((size_t)(bb * NHc + h)) * Sc + sI) * DHc + dd;
                    *(float2*)(outF + o) = v;
                }
            }
        }
    }
}

__global__ __launch_bounds__(256, 2)
void mma_gemm_qkv(const float* __restrict__ bq, const float* __restrict__ bk,
                  const float* __restrict__ bv)
{
    const int z = blockIdx.z;
    const float* bias = (z == 0) ? bq : (z == 1) ? bk : bv;
    float* out        = (z == 0) ? g_Qf : (z == 1) ? g_Kf : g_Vf;
    const float scale = (z == 0) ? (SCALE * LOG2E) : 1.0f;   // fold log2e for ex2 softmax
    mma_gemm_body<1>(g_Xhi, g_Xlo,
                     g_WtHi + (size_t)z * Hc * Hc, g_WtLo + (size_t)z * Hc * Hc,
                     bias, scale, out);
}

__global__ __launch_bounds__(256, 2)
void mma_gemm_out(const float* __restrict__ bo, float* __restrict__ out)
{
    mma_gemm_body<0>(g_Ahi, g_Alo,
                     g_WtHi + (size_t)3 * Hc * Hc, g_WtLo + (size_t)3 * Hc * Hc,
                     bo, 1.0f, out);
}

// =================== flash attention: pure tf32 HMMA, ldmatrix frags ========
// tf32 fragments loaded via ldmatrix by treating 4-float groups as 16B "b16
// rows": a-frag = x4 over (m-row, k-half) rows; b-frag = x2 over (n-row,
// k-half). Scores LDS instructions drop 24 -> 10 per ks-step, bytes equal.
// K-tile = 128 keys (two 64-key halves per staged buffer) halves barriers.
// exp via raw ex2 (log2e pre-folded into Q by the QKV epilogue).
#define QSTR 68                        // Q/K row stride words (272B)
#define VSTR 72                        // V row stride words (288B)
#define SM_Q 0
#define QBYTES (256 * QSTR * 4)        // 69632
#define SM_KV QBYTES
#define KTILE_B (128 * QSTR * 4)       // 34816
#define VTILE_B (128 * VSTR * 4)       // 36864
#define KVSTG (KTILE_B + VTILE_B)      // 71680
#define ATTN_SMEM (QBYTES + 2 * KVSTG) // 212992

__global__ __launch_bounds__(256, 1)
void attn_mma_kernel()
{
    extern __shared__ char smem[];
    const uint32_t sb = smem_u32(smem);

    const int tid = threadIdx.x, lane = tid & 31, wid = tid >> 5;
    const int head = blockIdx.y;
    const int q0   = blockIdx.x * 256;
    const int g = lane >> 2, tg = lane & 3;

    const float* Qp = g_Qf + ((size_t)head * Sc + q0) * DHc;
    const float* Kp = g_Kf + (size_t)head * Sc * DHc;
    const float* Vp = g_Vf + (size_t)head * Sc * DHc;

    // ---- prologue: stage Q (256x64 f32) + K/V tile 0 (128 keys) ----
    {
        #pragma unroll
        for (int p = 0; p < 16; p++) {                 // Q: 4096 16B chunks
            const int i = p * 256 + tid;
            const int r = i >> 4, c = i & 15;
            cp16(sb + SM_Q + (uint32_t)(r * QSTR * 4 + c * 16), Qp + r * DHc + c * 4);
        }
        const uint32_t kb = sb + SM_KV, vb = kb + KTILE_B;
        #pragma unroll
        for (int p = 0; p < 8; p++) {                  // K,V: 2048 chunks each
            const int i = p * 256 + tid;
            const int r = i >> 4, c = i & 15;
            cp16(kb + (uint32_t)(r * QSTR * 4 + c * 16), Kp + r * DHc + c * 4);
            cp16(vb + (uint32_t)(r * VSTR * 4 + c * 16), Vp + r * DHc + c * 4);
        }
        CP_COMMIT();
    }

    float O[2][8][4];
    #pragma unroll
    for (int mt = 0; mt < 2; mt++)
        #pragma unroll
        for (int j = 0; j < 8; j++)
            #pragma unroll
            for (int i = 0; i < 4; i++) O[mt][j][i] = 0.f;
    float lsum[2][2] = {{0.f, 0.f}, {0.f, 0.f}};

    // ldmatrix lane-address components
    const int lmrow  = lane & 15;              // a-frag: m-row within 16
    const int lmhalf = lane >> 4;              // a-frag: k-half (16B)
    const int lbrow  = lane & 7;               // b-frag: n-row within 8
    const int lbhalf = (lane >> 3) & 1;        // b-frag: k-half

    // shfl repack constants (c-frag cols 2tg,2tg+1 -> a-frag cols tg,tg+4)
    const uint32_t srcA = (uint32_t)((lane & ~3) | (tg >> 1));
    const uint32_t srcB = srcA + 2;
    const int selhi = tg & 1;

    #pragma unroll 1
    for (int kt = 0; kt < Sc / 128; kt++) {
        const uint32_t kb = sb + SM_KV + (uint32_t)(kt & 1) * KVSTG;
        const uint32_t vb = kb + KTILE_B;

        if (kt + 1 < Sc / 128) {
            const uint32_t kbn = sb + SM_KV + (uint32_t)((kt + 1) & 1) * KVSTG;
            const uint32_t vbn = kbn + KTILE_B;
            #pragma unroll
            for (int p = 0; p < 8; p++) {
                const int i = p * 256 + tid;
                const int r = i >> 4, c = i & 15;
                const float* ks = Kp + (size_t)((kt + 1) * 128 + r) * DHc + c * 4;
                const float* vs = Vp + (size_t)((kt + 1) * 128 + r) * DHc + c * 4;
                cp16(kbn + (uint32_t)(r * QSTR * 4 + c * 16), ks);
                cp16(vbn + (uint32_t)(r * VSTR * 4 + c * 16), vs);
            }
            CP_COMMIT();
            CP_WAIT(1);
        } else {
            CP_WAIT(0);
        }
        __syncthreads();

        #pragma unroll
        for (int half = 0; half < 2; half++) {
            const int koff = half * 64;

            // ---- scores: S = Q . K^T (tf32 k8, ldmatrix fragments) ----
            float S[2][8][4];
            #pragma unroll
            for (int mt = 0; mt < 2; mt++)
                #pragma unroll
                for (int j = 0; j < 8; j++)
                    #pragma unroll
                    for (int i = 0; i < 4; i++) S[mt][j][i] = 0.f;

            #pragma unroll
            for (int ks = 0; ks < 8; ks++) {
                const uint32_t kcol = (uint32_t)(ks * 32);
                uint32_t qa[2][4];
                #pragma unroll
                for (int mt = 0; mt < 2; mt++) {
                    const uint32_t qaddr = sb + SM_Q
                        + (uint32_t)((wid * 32 + mt * 16 + lmrow) * QSTR) * 4
                        + kcol + (uint32_t)lmhalf * 16;
                    ldm4(qa[mt], qaddr);
                }
                #pragma unroll
                for (int nb = 0; nb < 8; nb++) {
                    uint32_t bk[2];
                    const uint32_t kaddr = kb
                        + (uint32_t)((koff + nb * 8 + lbrow) * QSTR) * 4
                        + kcol + (uint32_t)lbhalf * 16;
                    ldm2(bk, kaddr);
                    mma_tf32(S[0][nb], qa[0], bk[0], bk[1]);
                    mma_tf32(S[1][nb], qa[1], bk[0], bk[1]);
                }
            }

            // ---- fused softmax (ex2) + PV per 8-key group t ----
            #pragma unroll
            for (int t = 0; t < 8; t++) {
                uint32_t aa[2][4];
                #pragma unroll
                for (int mt = 0; mt < 2; mt++) {
                    const float p0 = ex2f(S[mt][t][0]);
                    const float p1 = ex2f(S[mt][t][1]);
                    const float p2 = ex2f(S[mt][t][2]);
                    const float p3 = ex2f(S[mt][t][3]);
                    lsum[mt][0] += p0 + p1;
                    lsum[mt][1] += p2 + p3;
                    const uint32_t u0 = f2tf32(p0), u1 = f2tf32(p1);
                    const uint32_t u2 = f2tf32(p2), u3 = f2tf32(p3);
                    uint32_t x, y;
                    x = __shfl_sync(0xFFFFFFFFu, u0, srcA);
                    y = __shfl_sync(0xFFFFFFFFu, u1, srcA);
                    aa[mt][0] = selhi ? y : x;
                    x = __shfl_sync(0xFFFFFFFFu, u2, srcA);
                    y = __shfl_sync(0xFFFFFFFFu, u3, srcA);
                    aa[mt][1] = selhi ? y : x;
                    x = __shfl_sync(0xFFFFFFFFu, u0, srcB);
                    y = __shfl_sync(0xFFFFFFFFu, u1, srcB);
                    aa[mt][2] = selhi ? y : x;
                    x = __shfl_sync(0xFFFFFFFFu, u2, srcB);
                    y = __shfl_sync(0xFFFFFFFFu, u3, srcB);
                    aa[mt][3] = selhi ? y : x;
                }
                #pragma unroll
                for (int db = 0; db < 8; db++) {
                    const uint32_t vaddr = vb
                        + (uint32_t)(((koff + t * 8 + tg) * VSTR) + db * 8 + g) * 4;
                    const uint32_t b0 = lds32(vaddr);
                    const uint32_t b1 = lds32(vaddr + 4 * VSTR * 4);
                    mma_tf32(O[0][db], aa[0], b0, b1);
                    mma_tf32(O[1][db], aa[1], b0, b1);
                }
            }
        }
        __syncthreads();
    }

    // row-sum reduction across lanes sharing a row
    #pragma unroll
    for (int mt = 0; mt < 2; mt++) {
        lsum[mt][0] += __shfl_xor_sync(0xFFFFFFFFu, lsum[mt][0], 1);
        lsum[mt][0] += __shfl_xor_sync(0xFFFFFFFFu, lsum[mt][0], 2);
        lsum[mt][1] += __shfl_xor_sync(0xFFFFFFFFu, lsum[mt][1], 1);
        lsum[mt][1] += __shfl_xor_sync(0xFFFFFFFFu, lsum[mt][1], 2);
    }

    // write normalized output as hi/lo split into [b*S+s][H]
    const int b_idx = head / NHc, h = head % NHc;
    #pragma unroll
    for (int mt = 0; mt < 2; mt++) {
        const int row0 = q0 + wid * 32 + mt * 16 + g;
        const float inv0 = 1.f / lsum[mt][0], inv1 = 1.f / lsum[mt][1];
        #pragma unroll
        for (int j = 0; j < 8; j++) {
            const int dcol = h * DHc + j * 8 + tg * 2;
            {
                const float v0 = O[mt][j][0] * inv0, v1 = O[mt][j][1] * inv0;
                bf16 h0, l0, h1, l1;
                split1(v0, h0, l0); split1(v1, h1, l1);
                const size_t o = (size_t)(b_idx * Sc + row0) * Hc + dcol;
                *(__nv_bfloat162*)(g_Ahi + o) = __halves2bfloat162(h0, h1);
                *(__nv_bfloat162*)(g_Alo + o) = __halves2bfloat162(l0, l1);
            }
            {
                const float v2 = O[mt][j][2] * inv1, v3 = O[mt][j][3] * inv1;
                bf16 h2, l2, h3, l3;
                split1(v2, h2, l2); split1(v3, h3, l3);
                const size_t o = (size_t)(b_idx * Sc + row0 + 8) * Hc + dcol;
                *(__nv_bfloat162*)(g_Ahi + o) = __halves2bfloat162(h2, h3);
                *(__nv_bfloat162*)(g_Alo + o) = __halves2bfloat162(l2, l3);
            }
        }
    }
}

// ---------------------------------------------------------------------------
extern "C" void kernel_launch(void* const* d_in, const int* in_sizes, int n_in,
                              void* d_out, int out_size)
{
    const float* x  = (const float*)d_in[0];
    const float* Wq = (const float*)d_in[2];
    const float* bq = (const float*)d_in[3];
    const float* Wk = (const float*)d_in[4];
    const float* bk = (const float*)d_in[5];
    const float* Wv = (const float*)d_in[6];
    const float* bv = (const float*)d_in[7];
    const float* Wo = (const float*)d_in[8];
    const float* bo = (const float*)d_in[9];
    float* out = (float*)d_out;

    static bool attr_set = false;
    if (!attr_set) {
        cudaFuncSetAttribute(attn_mma_kernel,
                             cudaFuncAttributeMaxDynamicSharedMemorySize, ATTN_SMEM);
        attr_set = true;
    }

    // 0) split x and weights into bf16 hi/lo (weights transposed to [n][k])
    split_x_kernel<<<(Mc * Hc / 4) / 256, 256>>>(x);
    dim3 gw(Hc / 32, Hc / 32, 4);
    split_w_kernel<<<gw, 256>>>(Wq, Wk, Wv, Wo);

    // 1) QKV projections (split-bf16 HMMA) -> tf32 head layout, Q * SCALE*log2e
    dim3 g1(Hc / 128, Mc / 128, 3);
    mma_gemm_qkv<<<g1, 256>>>(bq, bk, bv);

    // 2) pure-tf32 flash attention, ldmatrix frags, 128-key double buffer
    dim3 g2(Sc / 256, Bc * NHc);
    attn_mma_kernel<<<g2, 256, ATTN_SMEM>>>();

    // 3) output projection (split-bf16 HMMA)
    dim3 g3(Hc / 128, Mc / 128);
    mma_gemm_out<<<g3, 256>>>(bo, out);
}